// round 1
// baseline (speedup 1.0000x reference)
#include <cuda_runtime.h>

#define S_  2048
#define B_  4
#define D_  256
#define NH_ 4
#define K_  1024
#define FF_ 1024
#define SB_ (S_*B_)

// ---------------- scratch (__device__ globals; no allocations allowed) ----------
static __device__ __align__(16) float g_wq[(size_t)NH_*SB_*K_];      // 128 MB [h][s*B+b][k]
static __device__ __align__(16) float g_wk[(size_t)NH_*SB_*K_];      // 128 MB
static __device__ __align__(16) float g_P [(size_t)NH_*B_*S_*S_];    // 256 MB exp(dot) [h*B+b][q][s]
static __device__ __align__(16) float g_invden[NH_*B_*S_];
static __device__ __align__(16) float g_aff0 [NH_*B_*S_];
static __device__ __align__(16) float g_ctx[NH_*B_*D_];
static __device__ __align__(16) float g_xh [NH_*B_*D_];
static __device__ __align__(16) float g_src2[B_*D_];
static __device__ __align__(16) float g_x  [SB_*D_];                 // 8 MB
static __device__ __align__(16) float g_h1 [(size_t)SB_*FF_];        // 32 MB
static __device__ __align__(16) float g_ff [SB_*D_];                 // 8 MB

// ---------------- helpers ----------------
__device__ __forceinline__ float blk_sum(float v, float* red, int nw) {
#pragma unroll
    for (int o = 16; o > 0; o >>= 1) v += __shfl_xor_sync(0xffffffffu, v, o);
    int w = threadIdx.x >> 5;
    if ((threadIdx.x & 31) == 0) red[w] = v;
    __syncthreads();
    float s = 0.f;
    for (int i = 0; i < nw; i++) s += red[i];
    __syncthreads();
    return s;
}

// layernorm over 256 threads (one value per thread), eps = 1e-5
__device__ __forceinline__ float ln256(float v, float g, float b, float* red) {
    float mean = blk_sum(v, red, 8) * (1.f/256.f);
    float dv = v - mean;
    float var = blk_sum(dv*dv, red, 8) * (1.f/256.f);
    return dv * rsqrtf(var + 1e-5f) * g + b;
}

// ---------------- 128x128x8 tiled fp32 GEMM core: C = epi(A @ B^T) ----------------
// A: [M,Kd] rows stride lda; B: [N,Kd] rows stride ldb; 256 threads, 8x8 microtile.
// ep: 0 none, 1 exp, 2 relu(bias), 3 bias
__device__ __forceinline__ void gemm128(
    const float* __restrict__ A, int lda,
    const float* __restrict__ Bw, int ldb,
    float* __restrict__ C, int ldc,
    int Kd, int m0, int n0, int ep, const float* __restrict__ bias)
{
    __shared__ __align__(16) float As[8][128];
    __shared__ __align__(16) float Bs[8][128];
    const int tid = threadIdx.x;
    const int tx = tid & 15;      // n micro-tile
    const int ty = tid >> 4;      // m micro-tile
    const int lr = tid >> 1;      // load row within tile (0..127)
    const int lc = (tid & 1) * 4; // load col (0 or 4)
    const float* Ap = A + (size_t)(m0 + lr) * lda + lc;
    const float* Bp = Bw + (size_t)(n0 + lr) * ldb + lc;

    float acc[8][8];
#pragma unroll
    for (int i = 0; i < 8; i++)
#pragma unroll
        for (int j = 0; j < 8; j++) acc[i][j] = 0.f;

    for (int kb = 0; kb < Kd; kb += 8) {
        float4 av = *(const float4*)(Ap + kb);
        float4 bv = *(const float4*)(Bp + kb);
        As[lc+0][lr] = av.x; As[lc+1][lr] = av.y; As[lc+2][lr] = av.z; As[lc+3][lr] = av.w;
        Bs[lc+0][lr] = bv.x; Bs[lc+1][lr] = bv.y; Bs[lc+2][lr] = bv.z; Bs[lc+3][lr] = bv.w;
        __syncthreads();
#pragma unroll
        for (int kk = 0; kk < 8; kk++) {
            float4 a0 = *(const float4*)&As[kk][ty*8];
            float4 a1 = *(const float4*)&As[kk][ty*8+4];
            float4 b0 = *(const float4*)&Bs[kk][tx*8];
            float4 b1 = *(const float4*)&Bs[kk][tx*8+4];
            float am[8] = {a0.x,a0.y,a0.z,a0.w,a1.x,a1.y,a1.z,a1.w};
            float bn[8] = {b0.x,b0.y,b0.z,b0.w,b1.x,b1.y,b1.z,b1.w};
#pragma unroll
            for (int i = 0; i < 8; i++)
#pragma unroll
                for (int j = 0; j < 8; j++)
                    acc[i][j] = fmaf(am[i], bn[j], acc[i][j]);
        }
        __syncthreads();
    }
#pragma unroll
    for (int i = 0; i < 8; i++) {
        int m = m0 + ty*8 + i;
#pragma unroll
        for (int j = 0; j < 8; j++) {
            int n = n0 + tx*8 + j;
            float v = acc[i][j];
            if (ep == 1)      v = __expf(v);
            else if (ep == 2) v = fmaxf(v + bias[n], 0.f);
            else if (ep == 3) v = v + bias[n];
            C[(size_t)m * ldc + n] = v;
        }
    }
}

// ---------------- stage kernels ----------------

// projections: wk = srcc @ WK[h]^T ; wq = memory @ WQ[h]^T  (unnormalized)
__global__ void __launch_bounds__(256, 2) k_proj(
    const float* __restrict__ srcc, const float* __restrict__ memory,
    const float* __restrict__ WK, const float* __restrict__ WQ)
{
    int z = blockIdx.z; int h = z & 3; int sel = z >> 2;
    const float* A = sel ? memory : srcc;                      // [SB, D]
    const float* W = (sel ? WQ : WK) + (size_t)h * K_ * D_;    // [K, D]
    float* C = (sel ? g_wq : g_wk) + (size_t)h * SB_ * K_;
    gemm128(A, D_, W, D_, C, K_, D_, blockIdx.y*128, blockIdx.x*128, 0, nullptr);
}

// in-place L2 row normalization of g_wk then g_wq (rows of length K_=1024); 128 thr
__global__ void k_l2norm() {
    __shared__ float red[4];
    size_t r = blockIdx.x;
    float* base = (r < (size_t)NH_*SB_) ? (g_wk + r*K_) : (g_wq + (r - (size_t)NH_*SB_)*K_);
    int t = threadIdx.x;
    float4 a = *(const float4*)(base + 4*t);
    float4 b = *(const float4*)(base + 512 + 4*t);
    float ss = a.x*a.x + a.y*a.y + a.z*a.z + a.w*a.w
             + b.x*b.x + b.y*b.y + b.z*b.z + b.w*b.w;
    ss = blk_sum(ss, red, 4);
    float sc = 1.f / fmaxf(sqrtf(ss), 1e-12f);
    a.x*=sc; a.y*=sc; a.z*=sc; a.w*=sc;
    b.x*=sc; b.y*=sc; b.z*=sc; b.w*=sc;
    *(float4*)(base + 4*t) = a;
    *(float4*)(base + 512 + 4*t) = b;
}

// Gram: P[q,s] = exp(wq[h,q,b,:] . wk[h,s,b,:]) for each (h,b)
__global__ void __launch_bounds__(256, 2) k_gram() {
    int z = blockIdx.z;                       // h*B + b
    int h = z >> 2, b = z & 3;
    const float* A  = g_wq + ((size_t)h * SB_ + b) * K_;   // row stride B*K
    const float* Bm = g_wk + ((size_t)h * SB_ + b) * K_;
    float* C = g_P + (size_t)z * S_ * S_;
    gemm128(A, B_*K_, Bm, B_*K_, C, S_, K_, blockIdx.y*128, blockIdx.x*128, 1, nullptr);
}

// softmax denominators: invden[row] = 1 / sum_s P[row, s]
__global__ void k_rowsum() {
    __shared__ float red[8];
    const float* row = g_P + (size_t)blockIdx.x * S_;
    int t = threadIdx.x;
    float4 a = *(const float4*)(row + 4*t);
    float4 b = *(const float4*)(row + 1024 + 4*t);
    float s = a.x+a.y+a.z+a.w + b.x+b.y+b.z+b.w;
    s = blk_sum(s, red, 8);
    if (t == 0) g_invden[blockIdx.x] = 1.f / s;
}

// column sums of softmax over q, then aff0[s] = softmax0[s] / (1e-9 + colsum[s])
__global__ void k_colsum() {
    __shared__ float sinv[S_];
    int z = blockIdx.y;
    const float* P = g_P + (size_t)z * S_ * S_;
    const float* inv = g_invden + z * S_;
    int t = threadIdx.x;
    for (int i = 0; i < 8; i++) sinv[i*256 + t] = inv[i*256 + t];
    __syncthreads();
    int s = blockIdx.x * 256 + t;
    float cs = 0.f;
#pragma unroll 4
    for (int q = 0; q < S_; q++)
        cs = fmaf(P[(size_t)q * S_ + s], sinv[q], cs);
    float a0 = P[s] * sinv[0];
    g_aff0[z * S_ + s] = a0 / (1e-9f + cs);
}

__global__ void k_ctx_zero() { g_ctx[blockIdx.x * 256 + threadIdx.x] = 0.f; }

// ctx[h,b,d] = sum_s aff0[h,b,s] * srcc[s,b,d]
__global__ void k_ctx(const float* __restrict__ srcc) {
    int z = blockIdx.y; int b = z & 3;
    int d = threadIdx.x;
    int s0 = blockIdx.x * 256;
    float acc = 0.f;
    for (int si = 0; si < 256; si++) {
        int s = s0 + si;
        acc = fmaf(g_aff0[z*S_ + s], srcc[((size_t)s*B_ + b)*D_ + d], acc);
    }
    atomicAdd(&g_ctx[z*D_ + d], acc);
}

// q=0 per-head chain: o = WV@ctx ; t = memory[0,b]-o ; ru = relu(Wt@t)
// hmid = relu(e1w@ru + e1b) ; s2 = e2w@hmid + e2b ; xh = LN(ru+s2; eg,eb)
__global__ void k_head(const float* __restrict__ memory,
                       const float* __restrict__ WV, const float* __restrict__ Wt,
                       const float* __restrict__ e1w, const float* __restrict__ e1b,
                       const float* __restrict__ e2w, const float* __restrict__ e2b,
                       const float* __restrict__ eg,  const float* __restrict__ eb)
{
    __shared__ float cx[256], tv[256], rus[256], hm[1024], red[8];
    int z = blockIdx.x; int h = z >> 2, b = z & 3;
    int t = threadIdx.x;
    cx[t] = g_ctx[z*D_ + t];
    __syncthreads();

    const float* wv = WV + ((size_t)h*D_ + t) * D_;
    float o = 0.f;
#pragma unroll 4
    for (int d = 0; d < D_; d++) o = fmaf(wv[d], cx[d], o);
    tv[t] = memory[(size_t)b * D_ + t] - o;          // memory[s=0,b,:]
    __syncthreads();

    const float* wt = Wt + ((size_t)h*D_ + t) * D_;
    float r = 0.f;
#pragma unroll 4
    for (int d = 0; d < D_; d++) r = fmaf(wt[d], tv[d], r);
    rus[t] = fmaxf(r, 0.f);
    __syncthreads();

#pragma unroll
    for (int i = 0; i < 4; i++) {
        int kx = i*256 + t;
        const float* w = e1w + ((size_t)h*K_ + kx) * D_;
        float v = e1b[h*K_ + kx];
#pragma unroll 4
        for (int d = 0; d < D_; d++) v = fmaf(w[d], rus[d], v);
        hm[kx] = fmaxf(v, 0.f);
    }
    __syncthreads();

    const float* w2 = e2w + ((size_t)h*D_ + t) * K_;
    float s2 = e2b[h*D_ + t];
#pragma unroll 4
    for (int kx = 0; kx < K_; kx++) s2 = fmaf(w2[kx], hm[kx], s2);

    float v = rus[t] + s2;
    g_xh[z*D_ + t] = ln256(v, eg[h*D_ + t], eb[h*D_ + t], red);
}

// srcc2[b,d] = sum_{h,e} xh[h,b,e] * Wout[d, h*256+e]
__global__ void k_out0(const float* __restrict__ Wout) {
    __shared__ float cat[1024];
    int b = blockIdx.x, d = threadIdx.x;
#pragma unroll
    for (int i = 0; i < 4; i++) cat[i*256 + d] = g_xh[(i*B_ + b)*D_ + d];
    __syncthreads();
    const float* w = Wout + (size_t)d * 1024;
    float acc = 0.f;
#pragma unroll 4
    for (int k = 0; k < 1024; k++) acc = fmaf(w[k], cat[k], acc);
    g_src2[b*D_ + d] = acc;
}

// x = LN(memory + srcc2[b]; n1g, n1b)
__global__ void k_ln1(const float* __restrict__ memory,
                      const float* __restrict__ n1g, const float* __restrict__ n1b) {
    __shared__ float red[8];
    int sb = blockIdx.x; int b = sb & 3; int t = threadIdx.x;
    float v = memory[(size_t)sb*D_ + t] + g_src2[b*D_ + t];
    g_x[(size_t)sb*D_ + t] = ln256(v, n1g[t], n1b[t], red);
}

// h1 = relu(x @ l1w^T + l1b)
__global__ void __launch_bounds__(256, 2) k_ffn1(const float* __restrict__ l1w,
                                                 const float* __restrict__ l1b) {
    gemm128(g_x, D_, l1w, D_, g_h1, FF_, D_, blockIdx.y*128, blockIdx.x*128, 2, l1b);
}

// ff = h1 @ l2w^T + l2b
__global__ void __launch_bounds__(256, 2) k_ffn2(const float* __restrict__ l2w,
                                                 const float* __restrict__ l2b) {
    gemm128(g_h1, FF_, l2w, FF_, g_ff, D_, FF_, blockIdx.y*128, blockIdx.x*128, 3, l2b);
}

// out = LN(x + ff; n3g, n3b)
__global__ void k_ln3(const float* __restrict__ n3g, const float* __restrict__ n3b,
                      float* __restrict__ out) {
    __shared__ float red[8];
    int sb = blockIdx.x; int t = threadIdx.x;
    float v = g_x[(size_t)sb*D_ + t] + g_ff[(size_t)sb*D_ + t];
    out[(size_t)sb*D_ + t] = ln256(v, n3g[t], n3b[t], red);
}

// ---------------- launch ----------------
extern "C" void kernel_launch(void* const* d_in, const int* in_sizes, int n_in,
                              void* d_out, int out_size) {
    (void)in_sizes; (void)n_in; (void)out_size;
    const float* srcc   = (const float*)d_in[0];
    const float* memory = (const float*)d_in[1];
    const float* WK   = (const float*)d_in[2];
    const float* WQ   = (const float*)d_in[3];
    const float* WV   = (const float*)d_in[4];
    const float* Wt   = (const float*)d_in[5];
    const float* e1w  = (const float*)d_in[6];
    const float* e1b  = (const float*)d_in[7];
    const float* e2w  = (const float*)d_in[8];
    const float* e2b  = (const float*)d_in[9];
    const float* eg   = (const float*)d_in[10];
    const float* eb   = (const float*)d_in[11];
    const float* Wout = (const float*)d_in[12];
    const float* l1w  = (const float*)d_in[13];
    const float* l1b  = (const float*)d_in[14];
    const float* l2w  = (const float*)d_in[15];
    const float* l2b  = (const float*)d_in[16];
    const float* n1g  = (const float*)d_in[17];
    const float* n1b  = (const float*)d_in[18];
    const float* n3g  = (const float*)d_in[19];
    const float* n3b  = (const float*)d_in[20];
    float* out = (float*)d_out;

    k_proj  <<<dim3(K_/128, SB_/128, 8), 256>>>(srcc, memory, WK, WQ);
    k_l2norm<<<2*NH_*SB_, 128>>>();
    k_gram  <<<dim3(S_/128, S_/128, NH_*B_), 256>>>();
    k_rowsum<<<NH_*B_*S_, 256>>>();
    k_colsum<<<dim3(S_/256, NH_*B_), 256>>>();
    k_ctx_zero<<<NH_*B_*D_/256, 256>>>();
    k_ctx   <<<dim3(S_/256, NH_*B_), 256>>>(srcc);
    k_head  <<<NH_*B_, 256>>>(memory, WV, Wt, e1w, e1b, e2w, e2b, eg, eb);
    k_out0  <<<B_, 256>>>(Wout);
    k_ln1   <<<SB_, 256>>>(memory, n1g, n1b);
    k_ffn1  <<<dim3(FF_/128, SB_/128), 256>>>(l1w, l1b);
    k_ffn2  <<<dim3(D_/128, SB_/128), 256>>>(l2w, l2b);
    k_ln3   <<<SB_, 256>>>(n3g, n3b, out);
}

// round 4
// speedup vs baseline: 3.5156x; 3.5156x over previous
#include <cuda_runtime.h>
#include <cuda_bf16.h>

typedef __nv_bfloat16 bf16;

#define S_  2048
#define B_  4
#define D_  256
#define NH_ 4
#define K_  1024
#define FF_ 1024
#define SB_ (S_*B_)
#define ZB_ (NH_*B_)

// ---------------- scratch ----------------
static __device__ __align__(16) bf16  g_wqh[(size_t)NH_*SB_*K_];   // 64 MB
static __device__ __align__(16) bf16  g_wkh[(size_t)NH_*SB_*K_];   // 64 MB
static __device__ __align__(16) float g_P  [(size_t)ZB_*S_*S_];    // 256 MB exp(dot)
static __device__ float g_rowsum[ZB_*S_];
static __device__ float g_inv   [ZB_*S_];
static __device__ float g_colsum[ZB_*S_];
static __device__ float g_aff0  [ZB_*S_];
static __device__ float g_ctx[ZB_*D_];
static __device__ float g_xh [ZB_*D_];
static __device__ float g_src2[B_*D_];
static __device__ __align__(16) float g_x  [SB_*D_];
static __device__ __align__(16) float g_h1 [(size_t)SB_*FF_];      // fp32 now
static __device__ __align__(16) float g_ff [SB_*D_];
// bf16 copies of inputs (attention path only)
static __device__ __align__(16) bf16 g_srcb[SB_*D_];
static __device__ __align__(16) bf16 g_memb[SB_*D_];
static __device__ __align__(16) bf16 g_WKb [NH_*K_*D_];
static __device__ __align__(16) bf16 g_WQb [NH_*K_*D_];

// ---------------- small helpers ----------------
__device__ __forceinline__ float blk_sum(float v, float* red, int nw) {
#pragma unroll
    for (int o = 16; o > 0; o >>= 1) v += __shfl_xor_sync(0xffffffffu, v, o);
    int w = threadIdx.x >> 5;
    if ((threadIdx.x & 31) == 0) red[w] = v;
    __syncthreads();
    float s = 0.f;
    for (int i = 0; i < nw; i++) s += red[i];
    __syncthreads();
    return s;
}
__device__ __forceinline__ float ln256(float v, float g, float b, float* red) {
    float mean = blk_sum(v, red, 8) * (1.f/256.f);
    float dv = v - mean;
    float var = blk_sum(dv*dv, red, 8) * (1.f/256.f);
    return dv * rsqrtf(var + 1e-5f) * g + b;
}
__device__ __forceinline__ unsigned sa(const void* p) {
    return (unsigned)__cvta_generic_to_shared(p);
}

// ---------------- bf16 tensor-core GEMM core ----------------
// C[M,N] = epi(A[M,Kd] @ B[N,Kd]^T), A/B bf16 K-contiguous, fp32 accum.
// Block 128x128, BK=32, 256 threads = 8 warps (warp tile 64x32, 2x4 grid).
// EP: 0 bf16 raw, 1 exp->f32 + rowsum atomics
template<int EP>
__device__ __forceinline__ void mma_core(
    const bf16* __restrict__ A, int lda,
    const bf16* __restrict__ Bw, int ldb,
    int Kd, int m0, int n0,
    float* __restrict__ outF, bf16* __restrict__ outH, int ldc,
    float* __restrict__ rowsum)
{
    __shared__ __align__(16) bf16 As[2][128][40];
    __shared__ __align__(16) bf16 Bs[2][128][40];

    const int tid  = threadIdx.x;
    const int lane = tid & 31;
    const int wid  = tid >> 5;
    const int wm0  = (wid & 1) * 64;
    const int wn0  = (wid >> 1) * 32;

    const int c0 = tid, c1 = tid + 256;
    const int ar0 = c0 >> 2, ak0 = (c0 & 3) * 8;
    const int ar1 = c1 >> 2, ak1 = (c1 & 3) * 8;

    float acc[4][4][4];
#pragma unroll
    for (int i = 0; i < 4; i++)
#pragma unroll
        for (int j = 0; j < 4; j++)
#pragma unroll
            for (int k = 0; k < 4; k++) acc[i][j][k] = 0.f;

    const int nK = Kd >> 5;

    {
        const bf16* a0 = A  + (size_t)(m0 + ar0) * lda + ak0;
        const bf16* a1 = A  + (size_t)(m0 + ar1) * lda + ak1;
        const bf16* b0 = Bw + (size_t)(n0 + ar0) * ldb + ak0;
        const bf16* b1 = Bw + (size_t)(n0 + ar1) * ldb + ak1;
        asm volatile("cp.async.cg.shared.global [%0],[%1],16;\n"::"r"(sa(&As[0][ar0][ak0])),"l"(a0));
        asm volatile("cp.async.cg.shared.global [%0],[%1],16;\n"::"r"(sa(&As[0][ar1][ak1])),"l"(a1));
        asm volatile("cp.async.cg.shared.global [%0],[%1],16;\n"::"r"(sa(&Bs[0][ar0][ak0])),"l"(b0));
        asm volatile("cp.async.cg.shared.global [%0],[%1],16;\n"::"r"(sa(&Bs[0][ar1][ak1])),"l"(b1));
        asm volatile("cp.async.commit_group;\n");
    }

    for (int kb = 0; kb < nK; kb++) {
        asm volatile("cp.async.wait_group 0;\n");
        __syncthreads();
        if (kb + 1 < nK) {
            int st = (kb + 1) & 1;
            int ko = (kb + 1) * 32;
            const bf16* a0 = A  + (size_t)(m0 + ar0) * lda + ko + ak0;
            const bf16* a1 = A  + (size_t)(m0 + ar1) * lda + ko + ak1;
            const bf16* b0 = Bw + (size_t)(n0 + ar0) * ldb + ko + ak0;
            const bf16* b1 = Bw + (size_t)(n0 + ar1) * ldb + ko + ak1;
            asm volatile("cp.async.cg.shared.global [%0],[%1],16;\n"::"r"(sa(&As[st][ar0][ak0])),"l"(a0));
            asm volatile("cp.async.cg.shared.global [%0],[%1],16;\n"::"r"(sa(&As[st][ar1][ak1])),"l"(a1));
            asm volatile("cp.async.cg.shared.global [%0],[%1],16;\n"::"r"(sa(&Bs[st][ar0][ak0])),"l"(b0));
            asm volatile("cp.async.cg.shared.global [%0],[%1],16;\n"::"r"(sa(&Bs[st][ar1][ak1])),"l"(b1));
            asm volatile("cp.async.commit_group;\n");
        }
        int st = kb & 1;
#pragma unroll
        for (int ks = 0; ks < 2; ks++) {
            unsigned a[4][4];
            unsigned bfr[4][2];
#pragma unroll
            for (int mt = 0; mt < 4; mt++) {
                unsigned ad = sa(&As[st][wm0 + mt*16 + (lane & 15)][ks*16 + (lane >> 4)*8]);
                asm volatile("ldmatrix.sync.aligned.m8n8.x4.shared.b16 {%0,%1,%2,%3},[%4];\n"
                    : "=r"(a[mt][0]), "=r"(a[mt][1]), "=r"(a[mt][2]), "=r"(a[mt][3]) : "r"(ad));
            }
#pragma unroll
            for (int bp = 0; bp < 2; bp++) {
                unsigned r0, r1, r2, r3;
                unsigned ad = sa(&Bs[st][wn0 + bp*16 + (lane & 15)][ks*16 + (lane >> 4)*8]);
                asm volatile("ldmatrix.sync.aligned.m8n8.x4.shared.b16 {%0,%1,%2,%3},[%4];\n"
                    : "=r"(r0), "=r"(r1), "=r"(r2), "=r"(r3) : "r"(ad));
                bfr[bp*2  ][0] = r0; bfr[bp*2  ][1] = r2;
                bfr[bp*2+1][0] = r1; bfr[bp*2+1][1] = r3;
            }
#pragma unroll
            for (int mt = 0; mt < 4; mt++)
#pragma unroll
                for (int nt = 0; nt < 4; nt++) {
                    asm volatile(
                        "mma.sync.aligned.m16n8k16.row.col.f32.bf16.bf16.f32 "
                        "{%0,%1,%2,%3},{%4,%5,%6,%7},{%8,%9},{%0,%1,%2,%3};\n"
                        : "+f"(acc[mt][nt][0]), "+f"(acc[mt][nt][1]),
                          "+f"(acc[mt][nt][2]), "+f"(acc[mt][nt][3])
                        : "r"(a[mt][0]), "r"(a[mt][1]), "r"(a[mt][2]), "r"(a[mt][3]),
                          "r"(bfr[nt][0]), "r"(bfr[nt][1]));
                }
        }
        __syncthreads();
    }

    // epilogue
    const int er = lane >> 2;
    const int ec = (lane & 3) * 2;
#pragma unroll
    for (int mt = 0; mt < 4; mt++) {
        float rsum0 = 0.f, rsum1 = 0.f;
#pragma unroll
        for (int nt = 0; nt < 4; nt++) {
            int m = m0 + wm0 + mt*16 + er;
            int n = n0 + wn0 + nt*8 + ec;
            float v0 = acc[mt][nt][0], v1 = acc[mt][nt][1];
            float v2 = acc[mt][nt][2], v3 = acc[mt][nt][3];
            if (EP == 1) {
                v0 = __expf(v0); v1 = __expf(v1); v2 = __expf(v2); v3 = __expf(v3);
                rsum0 += v0 + v1; rsum1 += v2 + v3;
                *(float2*)&outF[(size_t)m * ldc + n]       = make_float2(v0, v1);
                *(float2*)&outF[(size_t)(m+8) * ldc + n]   = make_float2(v2, v3);
            } else {
                *(__nv_bfloat162*)&outH[(size_t)m * ldc + n]     = __floats2bfloat162_rn(v0, v1);
                *(__nv_bfloat162*)&outH[(size_t)(m+8) * ldc + n] = __floats2bfloat162_rn(v2, v3);
            }
        }
        if (EP == 1) {
            rsum0 += __shfl_xor_sync(0xffffffffu, rsum0, 1);
            rsum0 += __shfl_xor_sync(0xffffffffu, rsum0, 2);
            rsum1 += __shfl_xor_sync(0xffffffffu, rsum1, 1);
            rsum1 += __shfl_xor_sync(0xffffffffu, rsum1, 2);
            if ((lane & 3) == 0) {
                atomicAdd(&rowsum[m0 + wm0 + mt*16 + er], rsum0);
                atomicAdd(&rowsum[m0 + wm0 + mt*16 + er + 8], rsum1);
            }
        }
    }
}

// ---------------- fp32 SIMT GEMM (FFN only; precision-critical) ----------------
// C = epi(A @ B^T); ep: 2 relu(bias), 3 bias
__device__ __forceinline__ void gemm128(
    const float* __restrict__ A, int lda,
    const float* __restrict__ Bw, int ldb,
    float* __restrict__ C, int ldc,
    int Kd, int m0, int n0, int ep, const float* __restrict__ bias)
{
    __shared__ __align__(16) float As[8][128];
    __shared__ __align__(16) float Bs[8][128];
    const int tid = threadIdx.x;
    const int tx = tid & 15;
    const int ty = tid >> 4;
    const int lr = tid >> 1;
    const int lc = (tid & 1) * 4;
    const float* Ap = A + (size_t)(m0 + lr) * lda + lc;
    const float* Bp = Bw + (size_t)(n0 + lr) * ldb + lc;

    float acc[8][8];
#pragma unroll
    for (int i = 0; i < 8; i++)
#pragma unroll
        for (int j = 0; j < 8; j++) acc[i][j] = 0.f;

    for (int kb = 0; kb < Kd; kb += 8) {
        float4 av = *(const float4*)(Ap + kb);
        float4 bv = *(const float4*)(Bp + kb);
        As[lc+0][lr] = av.x; As[lc+1][lr] = av.y; As[lc+2][lr] = av.z; As[lc+3][lr] = av.w;
        Bs[lc+0][lr] = bv.x; Bs[lc+1][lr] = bv.y; Bs[lc+2][lr] = bv.z; Bs[lc+3][lr] = bv.w;
        __syncthreads();
#pragma unroll
        for (int kk = 0; kk < 8; kk++) {
            float4 a0 = *(const float4*)&As[kk][ty*8];
            float4 a1 = *(const float4*)&As[kk][ty*8+4];
            float4 b0 = *(const float4*)&Bs[kk][tx*8];
            float4 b1 = *(const float4*)&Bs[kk][tx*8+4];
            float am[8] = {a0.x,a0.y,a0.z,a0.w,a1.x,a1.y,a1.z,a1.w};
            float bn[8] = {b0.x,b0.y,b0.z,b0.w,b1.x,b1.y,b1.z,b1.w};
#pragma unroll
            for (int i = 0; i < 8; i++)
#pragma unroll
                for (int j = 0; j < 8; j++)
                    acc[i][j] = fmaf(am[i], bn[j], acc[i][j]);
        }
        __syncthreads();
    }
#pragma unroll
    for (int i = 0; i < 8; i++) {
        int m = m0 + ty*8 + i;
#pragma unroll
        for (int j = 0; j < 8; j++) {
            int n = n0 + tx*8 + j;
            float v = acc[i][j] + bias[n];
            if (ep == 2) v = fmaxf(v, 0.f);
            C[(size_t)m * ldc + n] = v;
        }
    }
}

// ---------------- GEMM wrappers ----------------
__global__ void __launch_bounds__(256) k_proj() {
    int z = blockIdx.z; int h = z & 3; int sel = z >> 2;
    const bf16* A = sel ? g_memb : g_srcb;
    const bf16* W = (sel ? g_WQb : g_WKb) + (size_t)h * K_ * D_;
    bf16* C = (sel ? g_wqh : g_wkh) + (size_t)h * SB_ * K_;
    mma_core<0>(A, D_, W, D_, D_, blockIdx.y*128, blockIdx.x*128,
                nullptr, C, K_, nullptr);
}

__global__ void __launch_bounds__(256) k_gram() {
    int z = blockIdx.z; int h = z >> 2, b = z & 3;
    const bf16* A  = g_wqh + ((size_t)h * SB_ + b) * K_;
    const bf16* Bm = g_wkh + ((size_t)h * SB_ + b) * K_;
    float* C = g_P + (size_t)z * S_ * S_;
    mma_core<1>(A, B_*K_, Bm, B_*K_, K_, blockIdx.y*128, blockIdx.x*128,
                C, nullptr, S_, g_rowsum + z * S_);
}

__global__ void __launch_bounds__(256, 2) k_ffn1(const float* __restrict__ l1w,
                                                 const float* __restrict__ l1b) {
    gemm128(g_x, D_, l1w, D_, g_h1, FF_, D_, blockIdx.y*128, blockIdx.x*128, 2, l1b);
}

__global__ void __launch_bounds__(256, 2) k_ffn2(const float* __restrict__ l2w,
                                                 const float* __restrict__ l2b) {
    gemm128(g_h1, FF_, l2w, FF_, g_ff, D_, FF_, blockIdx.y*128, blockIdx.x*128, 3, l2b);
}

// ---------------- elementwise / reduction kernels ----------------
// dst selector: 0 srcb, 1 memb, 2 WKb, 3 WQb
__global__ void k_cvt(const float* __restrict__ src, int which, int n) {
    bf16* dst;
    switch (which) {
        case 0: dst = g_srcb; break;
        case 1: dst = g_memb; break;
        case 2: dst = g_WKb;  break;
        default: dst = g_WQb; break;
    }
    int i = blockIdx.x * 256 + threadIdx.x;
    if (i * 4 < n) {
        float4 v = *(const float4*)(src + i*4);
        ((__nv_bfloat162*)dst)[i*2]   = __floats2bfloat162_rn(v.x, v.y);
        ((__nv_bfloat162*)dst)[i*2+1] = __floats2bfloat162_rn(v.z, v.w);
    }
}

__global__ void k_zero3() {
    int i = blockIdx.x * 256 + threadIdx.x;
    if (i < ZB_*S_) { g_rowsum[i] = 0.f; g_colsum[i] = 0.f; }
    if (i < ZB_*D_) g_ctx[i] = 0.f;
}

// in-place bf16 L2 row normalization, rows of 1024; 128 threads/row
__global__ void k_l2norm() {
    __shared__ float red[4];
    size_t r = blockIdx.x;
    bf16* base = (r < (size_t)NH_*SB_) ? (g_wkh + r*K_) : (g_wqh + (r - (size_t)NH_*SB_)*K_);
    int t = threadIdx.x;
    uint4 u = *(uint4*)(base + 8*t);
    __nv_bfloat162* p = (__nv_bfloat162*)&u;
    float ss = 0.f;
    float vals[8];
#pragma unroll
    for (int i = 0; i < 4; i++) {
        float2 f = __bfloat1622float2(p[i]);
        vals[2*i] = f.x; vals[2*i+1] = f.y;
        ss += f.x*f.x + f.y*f.y;
    }
    ss = blk_sum(ss, red, 4);
    float sc = 1.f / fmaxf(sqrtf(ss), 1e-12f);
#pragma unroll
    for (int i = 0; i < 4; i++)
        p[i] = __floats2bfloat162_rn(vals[2*i]*sc, vals[2*i+1]*sc);
    *(uint4*)(base + 8*t) = u;
}

__global__ void k_inv() {
    int i = blockIdx.x * 256 + threadIdx.x;
    g_inv[i] = 1.f / g_rowsum[i];
}

// colsum: grid (S/256, ZB, S/128); block handles 256 s-cols x 128 q-rows
__global__ void k_colsum() {
    __shared__ float sinv[128];
    int z = blockIdx.y, qb = blockIdx.z;
    int t = threadIdx.x;
    if (t < 128) sinv[t] = g_inv[z*S_ + qb*128 + t];
    __syncthreads();
    int s = blockIdx.x * 256 + t;
    const float* P = g_P + (size_t)z*S_*S_ + (size_t)qb*128*S_ + s;
    float cs = 0.f;
#pragma unroll 4
    for (int q = 0; q < 128; q++)
        cs = fmaf(P[(size_t)q * S_], sinv[q], cs);
    atomicAdd(&g_colsum[z*S_ + s], cs);
}

__global__ void k_aff0() {
    int i = blockIdx.x * 256 + threadIdx.x;   // z*S + s
    int z = i >> 11;
    float a0 = g_P[(size_t)z*S_*S_ + (i & (S_-1))] * g_inv[z*S_];
    g_aff0[i] = a0 / (1e-9f + g_colsum[i]);
}

__global__ void k_ctx(const float* __restrict__ srcc) {
    int z = blockIdx.y; int b = z & 3;
    int d = threadIdx.x;
    int s0 = blockIdx.x * 256;
    float acc = 0.f;
    for (int si = 0; si < 256; si++) {
        int s = s0 + si;
        acc = fmaf(g_aff0[z*S_ + s], srcc[((size_t)s*B_ + b)*D_ + d], acc);
    }
    atomicAdd(&g_ctx[z*D_ + d], acc);
}

__global__ void k_head(const float* __restrict__ memory,
                       const float* __restrict__ WV, const float* __restrict__ Wt,
                       const float* __restrict__ e1w, const float* __restrict__ e1b,
                       const float* __restrict__ e2w, const float* __restrict__ e2b,
                       const float* __restrict__ eg,  const float* __restrict__ eb)
{
    __shared__ float cx[256], tv[256], rus[256], hm[1024], red[8];
    int z = blockIdx.x; int h = z >> 2, b = z & 3;
    int t = threadIdx.x;
    cx[t] = g_ctx[z*D_ + t];
    __syncthreads();

    const float* wv = WV + ((size_t)h*D_ + t) * D_;
    float o = 0.f;
#pragma unroll 4
    for (int d = 0; d < D_; d++) o = fmaf(wv[d], cx[d], o);
    tv[t] = memory[(size_t)b * D_ + t] - o;
    __syncthreads();

    const float* wt = Wt + ((size_t)h*D_ + t) * D_;
    float r = 0.f;
#pragma unroll 4
    for (int d = 0; d < D_; d++) r = fmaf(wt[d], tv[d], r);
    rus[t] = fmaxf(r, 0.f);
    __syncthreads();

#pragma unroll
    for (int i = 0; i < 4; i++) {
        int kx = i*256 + t;
        const float* w = e1w + ((size_t)h*K_ + kx) * D_;
        float v = e1b[h*K_ + kx];
#pragma unroll 4
        for (int d = 0; d < D_; d++) v = fmaf(w[d], rus[d], v);
        hm[kx] = fmaxf(v, 0.f);
    }
    __syncthreads();

    const float* w2 = e2w + ((size_t)h*D_ + t) * K_;
    float s2 = e2b[h*D_ + t];
#pragma unroll 4
    for (int kx = 0; kx < K_; kx++) s2 = fmaf(w2[kx], hm[kx], s2);

    float v = rus[t] + s2;
    g_xh[z*D_ + t] = ln256(v, eg[h*D_ + t], eb[h*D_ + t], red);
}

__global__ void k_out0(const float* __restrict__ Wout) {
    __shared__ float cat[1024];
    int b = blockIdx.x, d = threadIdx.x;
#pragma unroll
    for (int i = 0; i < 4; i++) cat[i*256 + d] = g_xh[(i*B_ + b)*D_ + d];
    __syncthreads();
    const float* w = Wout + (size_t)d * 1024;
    float acc = 0.f;
#pragma unroll 4
    for (int k = 0; k < 1024; k++) acc = fmaf(w[k], cat[k], acc);
    g_src2[b*D_ + d] = acc;
}

__global__ void k_ln1(const float* __restrict__ memory,
                      const float* __restrict__ n1g, const float* __restrict__ n1b) {
    __shared__ float red[8];
    int sb = blockIdx.x; int b = sb & 3; int t = threadIdx.x;
    float v = memory[(size_t)sb*D_ + t] + g_src2[b*D_ + t];
    g_x[(size_t)sb*D_ + t] = ln256(v, n1g[t], n1b[t], red);
}

__global__ void k_ln3(const float* __restrict__ n3g, const float* __restrict__ n3b,
                      float* __restrict__ out) {
    __shared__ float red[8];
    int sb = blockIdx.x; int t = threadIdx.x;
    float v = g_x[(size_t)sb*D_ + t] + g_ff[(size_t)sb*D_ + t];
    out[(size_t)sb*D_ + t] = ln256(v, n3g[t], n3b[t], red);
}

// ---------------- launch ----------------
extern "C" void kernel_launch(void* const* d_in, const int* in_sizes, int n_in,
                              void* d_out, int out_size) {
    (void)in_sizes; (void)n_in; (void)out_size;
    const float* srcc   = (const float*)d_in[0];
    const float* memory = (const float*)d_in[1];
    const float* WV   = (const float*)d_in[4];
    const float* Wt   = (const float*)d_in[5];
    const float* e1w  = (const float*)d_in[6];
    const float* e1b  = (const float*)d_in[7];
    const float* e2w  = (const float*)d_in[8];
    const float* e2b  = (const float*)d_in[9];
    const float* eg   = (const float*)d_in[10];
    const float* eb   = (const float*)d_in[11];
    const float* Wout = (const float*)d_in[12];
    const float* l1w  = (const float*)d_in[13];
    const float* l1b  = (const float*)d_in[14];
    const float* l2w  = (const float*)d_in[15];
    const float* l2b  = (const float*)d_in[16];
    const float* n1g  = (const float*)d_in[17];
    const float* n1b  = (const float*)d_in[18];
    const float* n3g  = (const float*)d_in[19];
    const float* n3b  = (const float*)d_in[20];
    float* out = (float*)d_out;

    k_zero3<<<(ZB_*S_ + 255)/256, 256>>>();
    k_cvt<<<SB_*D_/1024, 256>>>(srcc,   0, SB_*D_);
    k_cvt<<<SB_*D_/1024, 256>>>(memory, 1, SB_*D_);
    k_cvt<<<NH_*K_*D_/1024, 256>>>((const float*)d_in[2], 2, NH_*K_*D_);
    k_cvt<<<NH_*K_*D_/1024, 256>>>((const float*)d_in[3], 3, NH_*K_*D_);

    k_proj  <<<dim3(K_/128, SB_/128, 8), 256>>>();
    k_l2norm<<<2*NH_*SB_, 128>>>();
    k_gram  <<<dim3(S_/128, S_/128, ZB_), 256>>>();
    k_inv   <<<ZB_*S_/256, 256>>>();
    k_colsum<<<dim3(S_/256, ZB_, S_/128), 256>>>();
    k_aff0  <<<ZB_*S_/256, 256>>>();
    k_ctx   <<<dim3(S_/256, ZB_), 256>>>(srcc);
    k_head  <<<ZB_, 256>>>(memory, WV, Wt, e1w, e1b, e2w, e2b, eg, eb);
    k_out0  <<<B_, 256>>>(Wout);
    k_ln1   <<<SB_, 256>>>(memory, n1g, n1b);
    k_ffn1  <<<dim3(FF_/128, SB_/128), 256>>>(l1w, l1b);
    k_ffn2  <<<dim3(D_/128, SB_/128), 256>>>(l2w, l2b);
    k_ln3   <<<SB_, 256>>>(n3g, n3b, out);
}

// round 5
// speedup vs baseline: 3.8581x; 1.0974x over previous
#include <cuda_runtime.h>
#include <cuda_bf16.h>

typedef __nv_bfloat16 bf16;

#define S_  2048
#define B_  4
#define D_  256
#define NH_ 4
#define K_  1024
#define FF_ 1024
#define SB_ (S_*B_)
#define ZB_ (NH_*B_)

// ---------------- scratch ----------------
static __device__ __align__(16) bf16  g_wqh[(size_t)NH_*SB_*K_];   // 64 MB
static __device__ __align__(16) bf16  g_wkh[(size_t)NH_*SB_*K_];   // 64 MB
static __device__ __align__(16) float g_P  [(size_t)ZB_*S_*S_];    // 256 MB exp(dot)
static __device__ float g_rowsum[ZB_*S_];
static __device__ float g_inv   [ZB_*S_];
static __device__ float g_colsum[ZB_*S_];
static __device__ float g_aff0  [ZB_*S_];
static __device__ float g_ctx[ZB_*D_];
static __device__ float g_xh [ZB_*D_];
static __device__ float g_src2[B_*D_];
static __device__ __align__(16) float g_x  [SB_*D_];
static __device__ __align__(16) float g_ff [SB_*D_];
// split-bf16 FFN operands:  A' = [hi|hi|lo],  B' = [hi|lo|hi]
static __device__ __align__(16) bf16 g_xs  [(size_t)SB_*3*D_];     // 12.6 MB
static __device__ __align__(16) bf16 g_h1s [(size_t)SB_*3*FF_];    // 50 MB
static __device__ __align__(16) bf16 g_l1ws[(size_t)FF_*3*D_];
static __device__ __align__(16) bf16 g_l2ws[(size_t)D_*3*FF_];
// bf16 copies of inputs (attention path)
static __device__ __align__(16) bf16 g_srcb[SB_*D_];
static __device__ __align__(16) bf16 g_memb[SB_*D_];
static __device__ __align__(16) bf16 g_WKb [NH_*K_*D_];
static __device__ __align__(16) bf16 g_WQb [NH_*K_*D_];

// ---------------- small helpers ----------------
__device__ __forceinline__ float blk_sum(float v, float* red, int nw) {
#pragma unroll
    for (int o = 16; o > 0; o >>= 1) v += __shfl_xor_sync(0xffffffffu, v, o);
    int w = threadIdx.x >> 5;
    if ((threadIdx.x & 31) == 0) red[w] = v;
    __syncthreads();
    float s = 0.f;
    for (int i = 0; i < nw; i++) s += red[i];
    __syncthreads();
    return s;
}
__device__ __forceinline__ float ln256(float v, float g, float b, float* red) {
    float mean = blk_sum(v, red, 8) * (1.f/256.f);
    float dv = v - mean;
    float var = blk_sum(dv*dv, red, 8) * (1.f/256.f);
    return dv * rsqrtf(var + 1e-5f) * g + b;
}
__device__ __forceinline__ unsigned sa(const void* p) {
    return (unsigned)__cvta_generic_to_shared(p);
}
// exp(x) for x in [-1.05, 1.05]: degree-9 Taylor, rel err < 3e-6, all FMA-pipe
__device__ __forceinline__ float expp(float x) {
    float r = 2.7557319e-6f;                 // 1/9!
    r = fmaf(r, x, 2.4801587e-5f);           // 1/8!
    r = fmaf(r, x, 1.9841270e-4f);           // 1/7!
    r = fmaf(r, x, 1.3888889e-3f);           // 1/6!
    r = fmaf(r, x, 8.3333333e-3f);           // 1/5!
    r = fmaf(r, x, 4.1666667e-2f);           // 1/4!
    r = fmaf(r, x, 1.6666667e-1f);           // 1/3!
    r = fmaf(r, x, 0.5f);
    r = fmaf(r, x, 1.0f);
    r = fmaf(r, x, 1.0f);
    return r;
}

// ---------------- bf16 tensor-core GEMM core ----------------
// C[M,N] = epi(A[M,Kd] @ B[N,Kd]^T), A/B bf16 K-contiguous, fp32 accum.
// Block 128x128, BK=32, 256 threads = 8 warps (warp tile 64x32, 2x4 grid).
// EP: 0 bf16 raw, 1 exp(poly)->f32 + rowsum atomics,
//     2 relu+bias -> split triple bf16 (hi@n, hi@n+1024, lo@n+2048),
//     3 bias -> f32
template<int EP>
__device__ __forceinline__ void mma_core(
    const bf16* __restrict__ A, int lda,
    const bf16* __restrict__ Bw, int ldb,
    int Kd, int m0, int n0,
    float* __restrict__ outF, bf16* __restrict__ outH, int ldc,
    const float* __restrict__ bias, float* __restrict__ rowsum)
{
    __shared__ __align__(16) bf16 As[2][128][40];
    __shared__ __align__(16) bf16 Bs[2][128][40];

    const int tid  = threadIdx.x;
    const int lane = tid & 31;
    const int wid  = tid >> 5;
    const int wm0  = (wid & 1) * 64;
    const int wn0  = (wid >> 1) * 32;

    const int c0 = tid, c1 = tid + 256;
    const int ar0 = c0 >> 2, ak0 = (c0 & 3) * 8;
    const int ar1 = c1 >> 2, ak1 = (c1 & 3) * 8;

    float acc[4][4][4];
#pragma unroll
    for (int i = 0; i < 4; i++)
#pragma unroll
        for (int j = 0; j < 4; j++)
#pragma unroll
            for (int k = 0; k < 4; k++) acc[i][j][k] = 0.f;

    const int nK = Kd >> 5;

    {
        const bf16* a0 = A  + (size_t)(m0 + ar0) * lda + ak0;
        const bf16* a1 = A  + (size_t)(m0 + ar1) * lda + ak1;
        const bf16* b0 = Bw + (size_t)(n0 + ar0) * ldb + ak0;
        const bf16* b1 = Bw + (size_t)(n0 + ar1) * ldb + ak1;
        asm volatile("cp.async.cg.shared.global [%0],[%1],16;\n"::"r"(sa(&As[0][ar0][ak0])),"l"(a0));
        asm volatile("cp.async.cg.shared.global [%0],[%1],16;\n"::"r"(sa(&As[0][ar1][ak1])),"l"(a1));
        asm volatile("cp.async.cg.shared.global [%0],[%1],16;\n"::"r"(sa(&Bs[0][ar0][ak0])),"l"(b0));
        asm volatile("cp.async.cg.shared.global [%0],[%1],16;\n"::"r"(sa(&Bs[0][ar1][ak1])),"l"(b1));
        asm volatile("cp.async.commit_group;\n");
    }

    for (int kb = 0; kb < nK; kb++) {
        asm volatile("cp.async.wait_group 0;\n");
        __syncthreads();
        if (kb + 1 < nK) {
            int st = (kb + 1) & 1;
            int ko = (kb + 1) * 32;
            const bf16* a0 = A  + (size_t)(m0 + ar0) * lda + ko + ak0;
            const bf16* a1 = A  + (size_t)(m0 + ar1) * lda + ko + ak1;
            const bf16* b0 = Bw + (size_t)(n0 + ar0) * ldb + ko + ak0;
            const bf16* b1 = Bw + (size_t)(n0 + ar1) * ldb + ko + ak1;
            asm volatile("cp.async.cg.shared.global [%0],[%1],16;\n"::"r"(sa(&As[st][ar0][ak0])),"l"(a0));
            asm volatile("cp.async.cg.shared.global [%0],[%1],16;\n"::"r"(sa(&As[st][ar1][ak1])),"l"(a1));
            asm volatile("cp.async.cg.shared.global [%0],[%1],16;\n"::"r"(sa(&Bs[st][ar0][ak0])),"l"(b0));
            asm volatile("cp.async.cg.shared.global [%0],[%1],16;\n"::"r"(sa(&Bs[st][ar1][ak1])),"l"(b1));
            asm volatile("cp.async.commit_group;\n");
        }
        int st = kb & 1;
#pragma unroll
        for (int ks = 0; ks < 2; ks++) {
            unsigned a[4][4];
            unsigned bfr[4][2];
#pragma unroll
            for (int mt = 0; mt < 4; mt++) {
                unsigned ad = sa(&As[st][wm0 + mt*16 + (lane & 15)][ks*16 + (lane >> 4)*8]);
                asm volatile("ldmatrix.sync.aligned.m8n8.x4.shared.b16 {%0,%1,%2,%3},[%4];\n"
                    : "=r"(a[mt][0]), "=r"(a[mt][1]), "=r"(a[mt][2]), "=r"(a[mt][3]) : "r"(ad));
            }
#pragma unroll
            for (int bp = 0; bp < 2; bp++) {
                unsigned r0, r1, r2, r3;
                unsigned ad = sa(&Bs[st][wn0 + bp*16 + (lane & 15)][ks*16 + (lane >> 4)*8]);
                asm volatile("ldmatrix.sync.aligned.m8n8.x4.shared.b16 {%0,%1,%2,%3},[%4];\n"
                    : "=r"(r0), "=r"(r1), "=r"(r2), "=r"(r3) : "r"(ad));
                bfr[bp*2  ][0] = r0; bfr[bp*2  ][1] = r2;
                bfr[bp*2+1][0] = r1; bfr[bp*2+1][1] = r3;
            }
#pragma unroll
            for (int mt = 0; mt < 4; mt++)
#pragma unroll
                for (int nt = 0; nt < 4; nt++) {
                    asm volatile(
                        "mma.sync.aligned.m16n8k16.row.col.f32.bf16.bf16.f32 "
                        "{%0,%1,%2,%3},{%4,%5,%6,%7},{%8,%9},{%0,%1,%2,%3};\n"
                        : "+f"(acc[mt][nt][0]), "+f"(acc[mt][nt][1]),
                          "+f"(acc[mt][nt][2]), "+f"(acc[mt][nt][3])
                        : "r"(a[mt][0]), "r"(a[mt][1]), "r"(a[mt][2]), "r"(a[mt][3]),
                          "r"(bfr[nt][0]), "r"(bfr[nt][1]));
                }
        }
        __syncthreads();
    }

    // epilogue
    const int er = lane >> 2;
    const int ec = (lane & 3) * 2;
#pragma unroll
    for (int mt = 0; mt < 4; mt++) {
        float rsum0 = 0.f, rsum1 = 0.f;
#pragma unroll
        for (int nt = 0; nt < 4; nt++) {
            int m = m0 + wm0 + mt*16 + er;
            int n = n0 + wn0 + nt*8 + ec;
            float v0 = acc[mt][nt][0], v1 = acc[mt][nt][1];
            float v2 = acc[mt][nt][2], v3 = acc[mt][nt][3];
            if (EP == 1) {
                v0 = expp(v0); v1 = expp(v1); v2 = expp(v2); v3 = expp(v3);
                rsum0 += v0 + v1; rsum1 += v2 + v3;
                *(float2*)&outF[(size_t)m * ldc + n]       = make_float2(v0, v1);
                *(float2*)&outF[(size_t)(m+8) * ldc + n]   = make_float2(v2, v3);
            } else if (EP == 0) {
                *(__nv_bfloat162*)&outH[(size_t)m * ldc + n]     = __floats2bfloat162_rn(v0, v1);
                *(__nv_bfloat162*)&outH[(size_t)(m+8) * ldc + n] = __floats2bfloat162_rn(v2, v3);
            } else if (EP == 2) {
                float b0v = bias[n], b1v = bias[n+1];
                v0 = fmaxf(v0 + b0v, 0.f); v1 = fmaxf(v1 + b1v, 0.f);
                v2 = fmaxf(v2 + b0v, 0.f); v3 = fmaxf(v3 + b1v, 0.f);
                __nv_bfloat162 h01 = __floats2bfloat162_rn(v0, v1);
                __nv_bfloat162 h23 = __floats2bfloat162_rn(v2, v3);
                float2 f01 = __bfloat1622float2(h01);
                float2 f23 = __bfloat1622float2(h23);
                __nv_bfloat162 l01 = __floats2bfloat162_rn(v0 - f01.x, v1 - f01.y);
                __nv_bfloat162 l23 = __floats2bfloat162_rn(v2 - f23.x, v3 - f23.y);
                *(__nv_bfloat162*)&outH[(size_t)m * ldc + n]            = h01;
                *(__nv_bfloat162*)&outH[(size_t)m * ldc + n + 1024]     = h01;
                *(__nv_bfloat162*)&outH[(size_t)m * ldc + n + 2048]     = l01;
                *(__nv_bfloat162*)&outH[(size_t)(m+8) * ldc + n]        = h23;
                *(__nv_bfloat162*)&outH[(size_t)(m+8) * ldc + n + 1024] = h23;
                *(__nv_bfloat162*)&outH[(size_t)(m+8) * ldc + n + 2048] = l23;
            } else {
                float b0v = bias[n], b1v = bias[n+1];
                *(float2*)&outF[(size_t)m * ldc + n]     = make_float2(v0 + b0v, v1 + b1v);
                *(float2*)&outF[(size_t)(m+8) * ldc + n] = make_float2(v2 + b0v, v3 + b1v);
            }
        }
        if (EP == 1) {
            rsum0 += __shfl_xor_sync(0xffffffffu, rsum0, 1);
            rsum0 += __shfl_xor_sync(0xffffffffu, rsum0, 2);
            rsum1 += __shfl_xor_sync(0xffffffffu, rsum1, 1);
            rsum1 += __shfl_xor_sync(0xffffffffu, rsum1, 2);
            if ((lane & 3) == 0) {
                atomicAdd(&rowsum[m0 + wm0 + mt*16 + er], rsum0);
                atomicAdd(&rowsum[m0 + wm0 + mt*16 + er + 8], rsum1);
            }
        }
    }
}

// ---------------- GEMM wrappers ----------------
__global__ void __launch_bounds__(256) k_proj() {
    int z = blockIdx.z; int h = z & 3; int sel = z >> 2;
    const bf16* A = sel ? g_memb : g_srcb;
    const bf16* W = (sel ? g_WQb : g_WKb) + (size_t)h * K_ * D_;
    bf16* C = (sel ? g_wqh : g_wkh) + (size_t)h * SB_ * K_;
    mma_core<0>(A, D_, W, D_, D_, blockIdx.y*128, blockIdx.x*128,
                nullptr, C, K_, nullptr, nullptr);
}

__global__ void __launch_bounds__(256) k_gram() {
    int z = blockIdx.z; int h = z >> 2, b = z & 3;
    const bf16* A  = g_wqh + ((size_t)h * SB_ + b) * K_;
    const bf16* Bm = g_wkh + ((size_t)h * SB_ + b) * K_;
    float* C = g_P + (size_t)z * S_ * S_;
    mma_core<1>(A, B_*K_, Bm, B_*K_, K_, blockIdx.y*128, blockIdx.x*128,
                C, nullptr, S_, nullptr, g_rowsum + z * S_);
}

// ffn1: h1 = relu(x @ l1w^T + l1b) via split-bf16 (K = 3*256 = 768)
__global__ void __launch_bounds__(256) k_ffn1(const float* __restrict__ l1b) {
    mma_core<2>(g_xs, 3*D_, g_l1ws, 3*D_, 3*D_, blockIdx.y*128, blockIdx.x*128,
                nullptr, g_h1s, 3*FF_, l1b, nullptr);
}

// ffn2: ff = h1 @ l2w^T + l2b via split-bf16 (K = 3*1024 = 3072)
__global__ void __launch_bounds__(256) k_ffn2(const float* __restrict__ l2b) {
    mma_core<3>(g_h1s, 3*FF_, g_l2ws, 3*FF_, 3*FF_, blockIdx.y*128, blockIdx.x*128,
                g_ff, nullptr, D_, l2b, nullptr);
}

// ---------------- elementwise / reduction kernels ----------------
// dst selector: 0 srcb, 1 memb, 2 WKb, 3 WQb
__global__ void k_cvt(const float* __restrict__ src, int which, int n) {
    bf16* dst;
    switch (which) {
        case 0: dst = g_srcb; break;
        case 1: dst = g_memb; break;
        case 2: dst = g_WKb;  break;
        default: dst = g_WQb; break;
    }
    int i = blockIdx.x * 256 + threadIdx.x;
    if (i * 4 < n) {
        float4 v = *(const float4*)(src + i*4);
        ((__nv_bfloat162*)dst)[i*2]   = __floats2bfloat162_rn(v.x, v.y);
        ((__nv_bfloat162*)dst)[i*2+1] = __floats2bfloat162_rn(v.z, v.w);
    }
}

// weight split for FFN B' pattern [hi|lo|hi]:  which 0 = l1w (rows FF, len D), 1 = l2w (rows D, len FF)
__global__ void k_wsplit(const float* __restrict__ src, int which) {
    int len = which == 0 ? D_ : FF_;
    bf16* dst = which == 0 ? g_l1ws : g_l2ws;
    int i = blockIdx.x * 256 + threadIdx.x;
    int row = i / len, c = i % len;
    float v = src[i];
    bf16 hi = __float2bfloat16(v);
    bf16 lo = __float2bfloat16(v - __bfloat162float(hi));
    size_t base = (size_t)row * 3 * len;
    dst[base + c] = hi;
    dst[base + len + c] = lo;
    dst[base + 2*len + c] = hi;
}

__global__ void k_zero3() {
    int i = blockIdx.x * 256 + threadIdx.x;
    if (i < ZB_*S_) { g_rowsum[i] = 0.f; g_colsum[i] = 0.f; }
    if (i < ZB_*D_) g_ctx[i] = 0.f;
}

// in-place bf16 L2 row normalization, rows of 1024; 128 threads/row
__global__ void k_l2norm() {
    __shared__ float red[4];
    size_t r = blockIdx.x;
    bf16* base = (r < (size_t)NH_*SB_) ? (g_wkh + r*K_) : (g_wqh + (r - (size_t)NH_*SB_)*K_);
    int t = threadIdx.x;
    uint4 u = *(uint4*)(base + 8*t);
    __nv_bfloat162* p = (__nv_bfloat162*)&u;
    float ss = 0.f;
    float vals[8];
#pragma unroll
    for (int i = 0; i < 4; i++) {
        float2 f = __bfloat1622float2(p[i]);
        vals[2*i] = f.x; vals[2*i+1] = f.y;
        ss += f.x*f.x + f.y*f.y;
    }
    ss = blk_sum(ss, red, 4);
    float sc = 1.f / fmaxf(sqrtf(ss), 1e-12f);
#pragma unroll
    for (int i = 0; i < 4; i++)
        p[i] = __floats2bfloat162_rn(vals[2*i]*sc, vals[2*i+1]*sc);
    *(uint4*)(base + 8*t) = u;
}

__global__ void k_inv() {
    int i = blockIdx.x * 256 + threadIdx.x;
    g_inv[i] = 1.f / g_rowsum[i];
}

// colsum: grid (S/256, ZB, S/128); block handles 256 s-cols x 128 q-rows
__global__ void k_colsum() {
    __shared__ float sinv[128];
    int z = blockIdx.y, qb = blockIdx.z;
    int t = threadIdx.x;
    if (t < 128) sinv[t] = g_inv[z*S_ + qb*128 + t];
    __syncthreads();
    int s = blockIdx.x * 256 + t;
    const float* P = g_P + (size_t)z*S_*S_ + (size_t)qb*128*S_ + s;
    float cs = 0.f;
#pragma unroll 4
    for (int q = 0; q < 128; q++)
        cs = fmaf(P[(size_t)q * S_], sinv[q], cs);
    atomicAdd(&g_colsum[z*S_ + s], cs);
}

__global__ void k_aff0() {
    int i = blockIdx.x * 256 + threadIdx.x;   // z*S + s
    int z = i >> 11;
    float a0 = g_P[(size_t)z*S_*S_ + (i & (S_-1))] * g_inv[z*S_];
    g_aff0[i] = a0 / (1e-9f + g_colsum[i]);
}

__global__ void k_ctx(const float* __restrict__ srcc) {
    int z = blockIdx.y; int b = z & 3;
    int d = threadIdx.x;
    int s0 = blockIdx.x * 256;
    float acc = 0.f;
    for (int si = 0; si < 256; si++) {
        int s = s0 + si;
        acc = fmaf(g_aff0[z*S_ + s], srcc[((size_t)s*B_ + b)*D_ + d], acc);
    }
    atomicAdd(&g_ctx[z*D_ + d], acc);
}

__global__ void k_head(const float* __restrict__ memory,
                       const float* __restrict__ WV, const float* __restrict__ Wt,
                       const float* __restrict__ e1w, const float* __restrict__ e1b,
                       const float* __restrict__ e2w, const float* __restrict__ e2b,
                       const float* __restrict__ eg,  const float* __restrict__ eb)
{
    __shared__ float cx[256], tv[256], rus[256], hm[1024], red[8];
    int z = blockIdx.x; int h = z >> 2, b = z & 3;
    int t = threadIdx.x;
    cx[t] = g_ctx[z*D_ + t];
    __syncthreads();

    const float* wv = WV + ((size_t)h*D_ + t) * D_;
    float o = 0.f;
#pragma unroll 4
    for (int d = 0; d < D_; d++) o = fmaf(wv[d], cx[d], o);
    tv[t] = memory[(size_t)b * D_ + t] - o;
    __syncthreads();

    const float* wt = Wt + ((size_t)h*D_ + t) * D_;
    float r = 0.f;
#pragma unroll 4
    for (int d = 0; d < D_; d++) r = fmaf(wt[d], tv[d], r);
    rus[t] = fmaxf(r, 0.f);
    __syncthreads();

#pragma unroll
    for (int i = 0; i < 4; i++) {
        int kx = i*256 + t;
        const float* w = e1w + ((size_t)h*K_ + kx) * D_;
        float v = e1b[h*K_ + kx];
#pragma unroll 4
        for (int d = 0; d < D_; d++) v = fmaf(w[d], rus[d], v);
        hm[kx] = fmaxf(v, 0.f);
    }
    __syncthreads();

    const float* w2 = e2w + ((size_t)h*D_ + t) * K_;
    float s2 = e2b[h*D_ + t];
#pragma unroll 4
    for (int kx = 0; kx < K_; kx++) s2 = fmaf(w2[kx], hm[kx], s2);

    float v = rus[t] + s2;
    g_xh[z*D_ + t] = ln256(v, eg[h*D_ + t], eb[h*D_ + t], red);
}

__global__ void k_out0(const float* __restrict__ Wout) {
    __shared__ float cat[1024];
    int b = blockIdx.x, d = threadIdx.x;
#pragma unroll
    for (int i = 0; i < 4; i++) cat[i*256 + d] = g_xh[(i*B_ + b)*D_ + d];
    __syncthreads();
    const float* w = Wout + (size_t)d * 1024;
    float acc = 0.f;
#pragma unroll 4
    for (int k = 0; k < 1024; k++) acc = fmaf(w[k], cat[k], acc);
    g_src2[b*D_ + d] = acc;
}

// x = LN(memory + srcc2[b]); write fp32 x and split triple [xh|xh|xl]
__global__ void k_ln1(const float* __restrict__ memory,
                      const float* __restrict__ n1g, const float* __restrict__ n1b) {
    __shared__ float red[8];
    int sb = blockIdx.x; int b = sb & 3; int t = threadIdx.x;
    float v = memory[(size_t)sb*D_ + t] + g_src2[b*D_ + t];
    float x = ln256(v, n1g[t], n1b[t], red);
    g_x[(size_t)sb*D_ + t] = x;
    bf16 hi = __float2bfloat16(x);
    bf16 lo = __float2bfloat16(x - __bfloat162float(hi));
    size_t base = (size_t)sb * 3 * D_;
    g_xs[base + t] = hi;
    g_xs[base + D_ + t] = hi;
    g_xs[base + 2*D_ + t] = lo;
}

__global__ void k_ln3(const float* __restrict__ n3g, const float* __restrict__ n3b,
                      float* __restrict__ out) {
    __shared__ float red[8];
    int sb = blockIdx.x; int t = threadIdx.x;
    float v = g_x[(size_t)sb*D_ + t] + g_ff[(size_t)sb*D_ + t];
    out[(size_t)sb*D_ + t] = ln256(v, n3g[t], n3b[t], red);
}

// ---------------- launch ----------------
extern "C" void kernel_launch(void* const* d_in, const int* in_sizes, int n_in,
                              void* d_out, int out_size) {
    (void)in_sizes; (void)n_in; (void)out_size;
    const float* srcc   = (const float*)d_in[0];
    const float* memory = (const float*)d_in[1];
    const float* WV   = (const float*)d_in[4];
    const float* Wt   = (const float*)d_in[5];
    const float* e1w  = (const float*)d_in[6];
    const float* e1b  = (const float*)d_in[7];
    const float* e2w  = (const float*)d_in[8];
    const float* e2b  = (const float*)d_in[9];
    const float* eg   = (const float*)d_in[10];
    const float* eb   = (const float*)d_in[11];
    const float* Wout = (const float*)d_in[12];
    const float* l1w  = (const float*)d_in[13];
    const float* l1b  = (const float*)d_in[14];
    const float* l2w  = (const float*)d_in[15];
    const float* l2b  = (const float*)d_in[16];
    const float* n1g  = (const float*)d_in[17];
    const float* n1b  = (const float*)d_in[18];
    const float* n3g  = (const float*)d_in[19];
    const float* n3b  = (const float*)d_in[20];
    float* out = (float*)d_out;

    k_zero3<<<(ZB_*S_ + 255)/256, 256>>>();
    k_cvt<<<SB_*D_/1024, 256>>>(srcc,   0, SB_*D_);
    k_cvt<<<SB_*D_/1024, 256>>>(memory, 1, SB_*D_);
    k_cvt<<<NH_*K_*D_/1024, 256>>>((const float*)d_in[2], 2, NH_*K_*D_);
    k_cvt<<<NH_*K_*D_/1024, 256>>>((const float*)d_in[3], 3, NH_*K_*D_);
    k_wsplit<<<FF_*D_/256, 256>>>(l1w, 0);
    k_wsplit<<<D_*FF_/256, 256>>>(l2w, 1);

    k_proj  <<<dim3(K_/128, SB_/128, 8), 256>>>();
    k_l2norm<<<2*NH_*SB_, 128>>>();
    k_gram  <<<dim3(S_/128, S_/128, ZB_), 256>>>();
    k_inv   <<<ZB_*S_/256, 256>>>();
    k_colsum<<<dim3(S_/256, ZB_, S_/128), 256>>>();
    k_aff0  <<<ZB_*S_/256, 256>>>();
    k_ctx   <<<dim3(S_/256, ZB_), 256>>>(srcc);
    k_head  <<<ZB_, 256>>>(memory, WV, Wt, e1w, e1b, e2w, e2b, eg, eb);
    k_out0  <<<B_, 256>>>(Wout);
    k_ln1   <<<SB_, 256>>>(memory, n1g, n1b);
    k_ffn1  <<<dim3(FF_/128, SB_/128), 256>>>(l1b);
    k_ffn2  <<<dim3(D_/128, SB_/128), 256>>>(l2b);
    k_ln3   <<<SB_, 256>>>(n3g, n3b, out);
}